// round 15
// baseline (speedup 1.0000x reference)
#include <cuda_runtime.h>
#include <cuda_fp16.h>
#include <math.h>
#include <stdint.h>

#define HH 512
#define WW 512
#define CC 64
#define HW (HH*WW)
#define PW 516                 // padded H/W (reflect pad 2 materialized)
#define MPX 128                // pixels per CTA tile
#define NTHR 256

// smem layout (bytes)
#define ASTRIDE 144            // 64 ch * 2B payload, padded (ldmatrix conflict-free)
#define APX 132                // staged pixels per row (128 + halo 4)
#define SM_A    0
#define SM_B    (APX * ASTRIDE)                 // 19008
#define BSLOT   (64 * ASTRIDE)                  // 9216 per tap
#define SM_W3   (SM_B + 3 * BSLOT)              // 46656
#define SM_B3   (SM_W3 + 2304)                  // 48960
#define SM_TOTAL (SM_B3 + 256)                  // 49216
#define EPI_STRIDE 65                           // floats; sepi aliases [0, 33280)
#define SM_FLAG 33280                           // 128 bytes (MODE2 sd flags)
#define SM_MASK 33408                           // 5*132 floats (MODE1) -> ends 36048

typedef unsigned short ushort_t;

// ------------------------- device globals (no allocation) -------------------
__device__ __half g_xh[(size_t)PW * PW * CC];   // x, padded NHWC fp16
__device__ __half g_oh[(size_t)PW * PW * CC];   // x_ori, padded NHWC fp16
__device__ ushort_t g_w[2 * 9 * 4096];          // [conv][tap][ci*64+co] fp16

// ------------------------- helpers ------------------------------------------
__device__ __forceinline__ int reflect512(int i) {
    i = abs(i);
    return min(i, 1022 - i);
}
__device__ __forceinline__ float gelu_exact(float v) {
    return 0.5f * v * (1.0f + erff(v * 0.70710678118654752f));
}
__device__ __forceinline__ uint32_t smem_u32(const void* p) {
    uint32_t a;
    asm("{ .reg .u64 t; cvta.to.shared.u64 t, %1; cvt.u32.u64 %0, t; }" : "=r"(a) : "l"(p));
    return a;
}
__device__ __forceinline__ void cp16(uint32_t dst, const void* src) {
    asm volatile("cp.async.cg.shared.global [%0], [%1], 16;" :: "r"(dst), "l"(src));
}
__device__ __forceinline__ void cp_commit_wait() {
    asm volatile("cp.async.commit_group;");
    asm volatile("cp.async.wait_group 0;");
}
__device__ __forceinline__ void ldsm4(uint32_t (&r)[4], uint32_t addr) {
    asm volatile("ldmatrix.sync.aligned.m8n8.x4.shared.b16 {%0,%1,%2,%3}, [%4];"
                 : "=r"(r[0]), "=r"(r[1]), "=r"(r[2]), "=r"(r[3]) : "r"(addr));
}
__device__ __forceinline__ void ldsm4t(uint32_t (&r)[4], uint32_t addr) {
    asm volatile("ldmatrix.sync.aligned.m8n8.x4.trans.shared.b16 {%0,%1,%2,%3}, [%4];"
                 : "=r"(r[0]), "=r"(r[1]), "=r"(r[2]), "=r"(r[3]) : "r"(addr));
}
__device__ __forceinline__ void mma16816(float (&d)[4], const uint32_t (&a)[4],
                                         uint32_t b0, uint32_t b1) {
    asm volatile(
        "mma.sync.aligned.m16n8k16.row.col.f32.f16.f16.f32 "
        "{%0,%1,%2,%3}, {%4,%5,%6,%7}, {%8,%9}, {%0,%1,%2,%3};"
        : "+f"(d[0]), "+f"(d[1]), "+f"(d[2]), "+f"(d[3])
        : "r"(a[0]), "r"(a[1]), "r"(a[2]), "r"(a[3]), "r"(b0), "r"(b1));
}

// ------------------------- prepasses -----------------------------------------
// x (NCHW fp32) -> padded NHWC fp16
__global__ void prep_x(const float* __restrict__ x) {
    __shared__ ushort_t sh[32][66];
    const int yp  = blockIdx.y;
    const int xp0 = blockIdx.x * 32;
    const int tid = threadIdx.x;
    const int warp = tid >> 5, lane = tid & 31;
    const int ry = reflect512(yp - 2);
    const int xp = xp0 + lane;
    const int rx = reflect512((xp < PW ? xp : PW - 1) - 2);
    #pragma unroll
    for (int q = 0; q < 8; q++) {
        int ci = warp * 8 + q;
        float v = x[(size_t)ci * HW + (size_t)ry * WW + rx];
        sh[lane][ci] = __half_as_ushort(__float2half_rn(v));
    }
    __syncthreads();
    const int jj = tid >> 3, c0 = (tid & 7) * 8;
    const int xpw = xp0 + jj;
    if (xpw < PW) {
        size_t base = ((size_t)yp * PW + xpw) * 64 + c0;
        uint32_t a[4];
        #pragma unroll
        for (int i = 0; i < 4; i++)
            a[i] = (uint32_t)sh[jj][c0 + 2*i] | ((uint32_t)sh[jj][c0 + 2*i + 1] << 16);
        *reinterpret_cast<uint4*>(&g_xh[base]) = make_uint4(a[0], a[1], a[2], a[3]);
    }
}

// weights -> [conv][tap][ci][co] fp16
__global__ void prep_w(const float* __restrict__ w1, const float* __restrict__ w2) {
    int idx = blockIdx.x * 256 + threadIdx.x;
    if (idx >= 2 * 9 * 64 * 64) return;
    int conv = idx / 36864;
    int r    = idx % 36864;
    int tap  = r / 4096;
    int r2   = r % 4096;
    int co = r2 >> 6, ci = r2 & 63;
    const float* w = conv ? w2 : w1;
    float v = w[(co * 64 + ci) * 9 + tap];
    g_w[(size_t)(conv * 9 + tap) * 4096 + ci * 64 + co] =
        __half_as_ushort(__float2half_rn(v));
}

// ------------------------- conv via warp MMA (fp16, single pass) -------------
// CTA: 128 px, 8 warps; warp tile 32 px x 32 co (ph = warp>>1, ch = warp&1).
// MODE 1: g_xh -> g_oh = fp16( md ? gelu(conv+b1) : x )  [fused md + ring mirror]
// MODE 2: g_oh -> d_out = sd ? gelu(conv+b2)+x : gelu(dw(x)+b3)+x  [fp16 residual]
template <int MODE>
__global__ void __launch_bounds__(NTHR, 2) conv_mma(
    const float* __restrict__ bias,
    const float* __restrict__ mask,
    const float* __restrict__ w3,
    const float* __restrict__ b3,
    float* __restrict__ out)
{
    extern __shared__ __align__(16) char smem[];
    const uint32_t sb = smem_u32(smem);
    const int tid = threadIdx.x;
    const int warp = tid >> 5, lane = tid & 31;
    const int ph = warp >> 1;          // pixel quarter (0..3): px 32*ph..32*ph+31
    const int ch = warp & 1;           // co half (0: co 0-31, 1: co 32-63)
    const int x0 = blockIdx.x * MPX;
    const int y  = blockIdx.y;

    const __half* xin = (MODE == 1) ? g_xh : g_oh;
    const ushort_t* wbase = g_w + (size_t)((MODE == 1) ? 0 : 9) * 4096;

    // MODE 2: stage depthwise weights/bias once
    if (MODE == 2) {
        float* w3s = reinterpret_cast<float*>(smem + SM_W3);
        float* b3s = reinterpret_cast<float*>(smem + SM_B3);
        if (tid < 64) {
            #pragma unroll
            for (int t = 0; t < 9; t++) w3s[t * 64 + tid] = w3[tid * 9 + t];
            b3s[tid] = b3[tid];
        }
    }

    const uint32_t a_off = (uint32_t)(lane & 15) * ASTRIDE + (uint32_t)(lane >> 4) * 16;
    const uint32_t b_off = (uint32_t)((lane & 7) + ((lane >> 3) & 1) * 8) * ASTRIDE
                         + (uint32_t)(lane >> 4) * 16;

    float acc[2][4][4];
    #pragma unroll
    for (int mt = 0; mt < 2; mt++)
        #pragma unroll
        for (int nt = 0; nt < 4; nt++)
            #pragma unroll
            for (int i = 0; i < 4; i++) acc[mt][nt][i] = 0.0f;

    for (int dyi = 0; dyi < 3; dyi++) {
        __syncthreads();
        // ---- stage A: padded row y + 2*dyi, APX px ----
        {
            const char* src = reinterpret_cast<const char*>(
                &xin[((size_t)(y + 2 * dyi) * PW + x0) * 64]);
            #pragma unroll
            for (int it = 0; it < 5; it++) {
                int i = tid + it * NTHR;
                if (i < APX * 8) {
                    int px = i >> 3, seg = i & 7;
                    cp16(sb + SM_A + px * ASTRIDE + seg * 16, src + i * 16);
                }
            }
        }
        // ---- stage B: 3 taps of this dy-row ----
        {
            const char* src = reinterpret_cast<const char*>(wbase + (size_t)(3 * dyi) * 4096);
            #pragma unroll
            for (int it = 0; it < 6; it++) {
                int i = tid + it * NTHR;
                int slot = i >> 9;
                int rem  = i & 511;
                int ci = rem >> 3, seg = rem & 7;
                cp16(sb + SM_B + slot * BSLOT + ci * ASTRIDE + seg * 16, src + i * 16);
            }
        }
        cp_commit_wait();
        __syncthreads();

        #pragma unroll
        for (int dxi = 0; dxi < 3; dxi++) {
            const uint32_t am0 = sb + SM_A + (uint32_t)(32 * ph + 2 * dxi) * ASTRIDE + a_off;
            const uint32_t bb  = sb + SM_B + (uint32_t)dxi * BSLOT + (uint32_t)ch * 64 + b_off;
            #pragma unroll
            for (int kc = 0; kc < 64; kc += 16) {
                uint32_t ah0[4], ah1[4];
                ldsm4(ah0, am0 + kc * 2);
                ldsm4(ah1, am0 + 16 * ASTRIDE + kc * 2);
                const uint32_t bbase = bb + (uint32_t)kc * ASTRIDE;
                uint32_t bh0[4], bh1[4];
                ldsm4t(bh0, bbase);
                ldsm4t(bh1, bbase + 32);
                mma16816(acc[0][0], ah0, bh0[0], bh0[1]);
                mma16816(acc[0][1], ah0, bh0[2], bh0[3]);
                mma16816(acc[0][2], ah0, bh1[0], bh1[1]);
                mma16816(acc[0][3], ah0, bh1[2], bh1[3]);
                mma16816(acc[1][0], ah1, bh0[0], bh0[1]);
                mma16816(acc[1][1], ah1, bh0[2], bh0[3]);
                mma16816(acc[1][2], ah1, bh1[0], bh1[1]);
                mma16816(acc[1][3], ah1, bh1[2], bh1[3]);
            }
        }
    }

    // ---- epilogue: fragments -> smem (pixel-major) ----
    __syncthreads();
    float* sepi = reinterpret_cast<float*>(smem);
    #pragma unroll
    for (int mt = 0; mt < 2; mt++) {
        const int r = 32 * ph + 16 * mt + (lane >> 2);
        #pragma unroll
        for (int nt = 0; nt < 4; nt++) {
            const int c = 32 * ch + 8 * nt + 2 * (lane & 3);
            sepi[r * EPI_STRIDE + c]           = acc[mt][nt][0];
            sepi[r * EPI_STRIDE + c + 1]       = acc[mt][nt][1];
            sepi[(r + 8) * EPI_STRIDE + c]     = acc[mt][nt][2];
            sepi[(r + 8) * EPI_STRIDE + c + 1] = acc[mt][nt][3];
        }
    }

    const int m   = tid & 127;         // this thread's pixel
    const int chb = (tid >> 7) * 32;   // channel half base
    const int x = x0 + m;
    const int p = y * WW + x;
    const size_t ob = ((size_t)(y + 2) * PW + (x + 2)) * 64 + chb;

    if (MODE == 1) {
        // fused mask dilation: stage clipped 5x132 mask window
        float* smask = reinterpret_cast<float*>(smem + SM_MASK);
        for (int i = tid; i < 5 * 132; i += NTHR) {
            int r = i / 132, c = i - r * 132;
            int gy = y - 2 + r, gx = x0 - 2 + c;
            smask[i] = ((unsigned)gy < HH && (unsigned)gx < WW)
                     ? mask[gy * WW + gx] : 0.0f;
        }
        __syncthreads();
        const float* arow = &sepi[m * EPI_STRIDE];
        float mx = 0.0f;
        #pragma unroll
        for (int r = 0; r < 5; r++)
            #pragma unroll
            for (int c = 0; c < 5; c++)
                mx = fmaxf(mx, smask[r * 132 + m + c]);
        const bool md = mx > 0.5f;

        uint4 v[4];
        if (md) {
            #pragma unroll
            for (int i = 0; i < 4; i++) {
                uint32_t w[4];
                #pragma unroll
                for (int q = 0; q < 4; q++) {
                    const int c0 = chb + 8 * i + 2 * q;
                    float v0 = gelu_exact(arow[c0]     + __ldg(&bias[c0]));
                    float v1 = gelu_exact(arow[c0 + 1] + __ldg(&bias[c0 + 1]));
                    w[q] = (uint32_t)__half_as_ushort(__float2half_rn(v0))
                         | ((uint32_t)__half_as_ushort(__float2half_rn(v1)) << 16);
                }
                v[i] = make_uint4(w[0], w[1], w[2], w[3]);
            }
        } else {
            const uint4* shp = reinterpret_cast<const uint4*>(&g_xh[ob]);
            #pragma unroll
            for (int i = 0; i < 4; i++) v[i] = shp[i];
        }
        uint4* dh = reinterpret_cast<uint4*>(&g_oh[ob]);
        #pragma unroll
        for (int i = 0; i < 4; i++) dh[i] = v[i];

        // fused reflect-ring mirror
        int yr = -1, xr = -1;
        if (y == 1 || y == 2) yr = 2 - y;
        else if (y == 509 || y == 510) yr = 1024 - y;
        if (x == 1 || x == 2) xr = 2 - x;
        else if (x == 509 || x == 510) xr = 1024 - x;
        if (yr >= 0) {
            uint4* d = reinterpret_cast<uint4*>(&g_oh[((size_t)yr * PW + (x + 2)) * 64 + chb]);
            #pragma unroll
            for (int i = 0; i < 4; i++) d[i] = v[i];
        }
        if (xr >= 0) {
            uint4* d = reinterpret_cast<uint4*>(&g_oh[((size_t)(y + 2) * PW + xr) * 64 + chb]);
            #pragma unroll
            for (int i = 0; i < 4; i++) d[i] = v[i];
        }
        if (yr >= 0 && xr >= 0) {
            uint4* d = reinterpret_cast<uint4*>(&g_oh[((size_t)yr * PW + xr) * 64 + chb]);
            #pragma unroll
            for (int i = 0; i < 4; i++) d[i] = v[i];
        }
    } else {
        // ---- MODE 2: flags, coalesced dw into sepi at ~sd pixels, unified write
        unsigned char* sflag = reinterpret_cast<unsigned char*>(smem + SM_FLAG);
        if (tid < 128) sflag[tid] = (mask[y * WW + x0 + tid] > 0.5f) ? 1 : 0;
        __syncthreads();

        const float* w3s = reinterpret_cast<const float*>(smem + SM_W3);
        const float* b3s = reinterpret_cast<const float*>(smem + SM_B3);

        // cooperative dw: 8 threads per pixel (thread = (px, seg)); 32 px per pass
        const int seg = tid & 7;
        #pragma unroll
        for (int pass = 0; pass < 4; pass++) {
            const int px = pass * 32 + (tid >> 3);
            if (!sflag[px]) {
                const int gx2 = x0 + px;
                float a8[8];
                #pragma unroll
                for (int i = 0; i < 8; i++) a8[i] = 0.0f;
                #pragma unroll
                for (int t = 0; t < 9; t++) {
                    const size_t pos =
                        ((size_t)(y + 2 * (t / 3)) * PW + (gx2 + 2 * (t % 3))) * 64 + seg * 8;
                    uint4 v = *reinterpret_cast<const uint4*>(&g_xh[pos]);
                    const __half2* h = reinterpret_cast<const __half2*>(&v);
                    const float* wr = &w3s[t * 64 + seg * 8];
                    #pragma unroll
                    for (int j = 0; j < 4; j++) {
                        float2 f = __half22float2(h[j]);
                        a8[2*j]     = fmaf(f.x, wr[2*j],     a8[2*j]);
                        a8[2*j + 1] = fmaf(f.y, wr[2*j + 1], a8[2*j + 1]);
                    }
                }
                float* d = &sepi[px * EPI_STRIDE + seg * 8];
                #pragma unroll
                for (int j = 0; j < 8; j++) d[j] = a8[j];
            }
        }
        __syncthreads();

        // unified coalesced write; residual from g_xh (fp16)
        const bool sd = (sflag[m] != 0);
        const float* arow = &sepi[m * EPI_STRIDE];
        float xf[32];
        {
            const uint4* xr16 = reinterpret_cast<const uint4*>(&g_xh[ob]);
            #pragma unroll
            for (int i = 0; i < 4; i++) {
                uint4 v = xr16[i];
                const __half2* h = reinterpret_cast<const __half2*>(&v);
                #pragma unroll
                for (int j = 0; j < 4; j++) {
                    float2 f = __half22float2(h[j]);
                    xf[i * 8 + 2 * j]     = f.x;
                    xf[i * 8 + 2 * j + 1] = f.y;
                }
            }
        }
        #pragma unroll 8
        for (int j = 0; j < 32; j++) {
            const int c = chb + j;
            const float b = sd ? __ldg(&bias[c]) : b3s[c];
            const size_t o = (size_t)c * HW + p;
            out[o] = gelu_exact(arow[c] + b) + xf[j];
        }
    }
}

// ------------------------- launch --------------------------------------------
extern "C" void kernel_launch(void* const* d_in, const int* in_sizes, int n_in,
                              void* d_out, int out_size) {
    const float* x    = (const float*)d_in[0];
    const float* mask = (const float*)d_in[1];
    const float* w1   = (const float*)d_in[2];
    const float* b1   = (const float*)d_in[3];
    const float* w2   = (const float*)d_in[4];
    const float* b2   = (const float*)d_in[5];
    const float* w3   = (const float*)d_in[6];
    const float* b3   = (const float*)d_in[7];
    float* out = (float*)d_out;

    static bool attr_set = false;
    if (!attr_set) {
        cudaFuncSetAttribute(conv_mma<1>,
            cudaFuncAttributeMaxDynamicSharedMemorySize, SM_TOTAL);
        cudaFuncSetAttribute(conv_mma<2>,
            cudaFuncAttributeMaxDynamicSharedMemorySize, SM_TOTAL);
        attr_set = true;
    }

    prep_w<<<(2 * 9 * 64 * 64 + 255) / 256, 256>>>(w1, w2);
    prep_x<<<dim3((PW + 31) / 32, PW), 256>>>(x);

    dim3 cgrid(WW / MPX, HH);   // 4 x 512

    conv_mma<1><<<cgrid, NTHR, SM_TOTAL>>>(b1, mask, w3, b3, out);
    conv_mma<2><<<cgrid, NTHR, SM_TOTAL>>>(b2, mask, w3, b3, out);
}

// round 16
// speedup vs baseline: 1.1124x; 1.1124x over previous
#include <cuda_runtime.h>
#include <cuda_fp16.h>
#include <math.h>
#include <stdint.h>

#define HH 512
#define WW 512
#define CC 64
#define HW (HH*WW)
#define PW 516                 // padded H/W (reflect pad 2 materialized)
#define MPX 128                // pixels per CTA tile
#define NTHR 128

// smem layout (bytes)
#define ASTRIDE 144            // 64 ch * 2B payload, padded (ldmatrix conflict-free)
#define APX 132                // staged pixels per row (128 + halo 4)
#define SM_A    0
#define SM_B    (APX * ASTRIDE)                 // 19008
#define BSLOT   (64 * ASTRIDE)                  // 9216 per tap
#define SM_W3   (SM_B + 3 * BSLOT)              // 46656
#define SM_B3   (SM_W3 + 2304)                  // 48960
#define SM_TOTAL (SM_B3 + 256)                  // 49216
#define EPI_STRIDE 65                           // floats; sepi aliases [0, 33280)
#define SM_FLAG 33280                           // 128 bytes (MODE2 sd flags)
#define SM_MASK 33408                           // 5*132 floats (MODE1) -> ends 36048

typedef unsigned short ushort_t;

// ------------------------- device globals (no allocation) -------------------
__device__ __half g_xh[(size_t)PW * PW * CC];   // x, padded NHWC fp16
__device__ __half g_oh[(size_t)PW * PW * CC];   // x_ori, padded NHWC fp16
__device__ ushort_t g_w[2 * 9 * 4096];          // [conv][tap][ci*64+co] fp16

// ------------------------- helpers ------------------------------------------
__device__ __forceinline__ int reflect512(int i) {
    i = abs(i);
    return min(i, 1022 - i);
}
__device__ __forceinline__ float gelu_exact(float v) {
    return 0.5f * v * (1.0f + erff(v * 0.70710678118654752f));
}
__device__ __forceinline__ uint32_t smem_u32(const void* p) {
    uint32_t a;
    asm("{ .reg .u64 t; cvta.to.shared.u64 t, %1; cvt.u32.u64 %0, t; }" : "=r"(a) : "l"(p));
    return a;
}
__device__ __forceinline__ void cp16(uint32_t dst, const void* src) {
    asm volatile("cp.async.cg.shared.global [%0], [%1], 16;" :: "r"(dst), "l"(src));
}
__device__ __forceinline__ void cp_commit_wait() {
    asm volatile("cp.async.commit_group;");
    asm volatile("cp.async.wait_group 0;");
}
__device__ __forceinline__ void ldsm4(uint32_t (&r)[4], uint32_t addr) {
    asm volatile("ldmatrix.sync.aligned.m8n8.x4.shared.b16 {%0,%1,%2,%3}, [%4];"
                 : "=r"(r[0]), "=r"(r[1]), "=r"(r[2]), "=r"(r[3]) : "r"(addr));
}
__device__ __forceinline__ void ldsm4t(uint32_t (&r)[4], uint32_t addr) {
    asm volatile("ldmatrix.sync.aligned.m8n8.x4.trans.shared.b16 {%0,%1,%2,%3}, [%4];"
                 : "=r"(r[0]), "=r"(r[1]), "=r"(r[2]), "=r"(r[3]) : "r"(addr));
}
__device__ __forceinline__ void mma16816(float (&d)[4], const uint32_t (&a)[4],
                                         uint32_t b0, uint32_t b1) {
    asm volatile(
        "mma.sync.aligned.m16n8k16.row.col.f32.f16.f16.f32 "
        "{%0,%1,%2,%3}, {%4,%5,%6,%7}, {%8,%9}, {%0,%1,%2,%3};"
        : "+f"(d[0]), "+f"(d[1]), "+f"(d[2]), "+f"(d[3])
        : "r"(a[0]), "r"(a[1]), "r"(a[2]), "r"(a[3]), "r"(b0), "r"(b1));
}

// ------------------------- prepasses -----------------------------------------
// x (NCHW fp32) -> padded NHWC fp16
__global__ void prep_x(const float* __restrict__ x) {
    __shared__ ushort_t sh[32][66];
    const int yp  = blockIdx.y;
    const int xp0 = blockIdx.x * 32;
    const int tid = threadIdx.x;
    const int warp = tid >> 5, lane = tid & 31;
    const int ry = reflect512(yp - 2);
    const int xp = xp0 + lane;
    const int rx = reflect512((xp < PW ? xp : PW - 1) - 2);
    #pragma unroll
    for (int q = 0; q < 8; q++) {
        int ci = warp * 8 + q;
        float v = x[(size_t)ci * HW + (size_t)ry * WW + rx];
        sh[lane][ci] = __half_as_ushort(__float2half_rn(v));
    }
    __syncthreads();
    const int jj = tid >> 3, c0 = (tid & 7) * 8;
    const int xpw = xp0 + jj;
    if (xpw < PW) {
        size_t base = ((size_t)yp * PW + xpw) * 64 + c0;
        uint32_t a[4];
        #pragma unroll
        for (int i = 0; i < 4; i++)
            a[i] = (uint32_t)sh[jj][c0 + 2*i] | ((uint32_t)sh[jj][c0 + 2*i + 1] << 16);
        *reinterpret_cast<uint4*>(&g_xh[base]) = make_uint4(a[0], a[1], a[2], a[3]);
    }
}

// weights -> [conv][tap][ci][co] fp16
__global__ void prep_w(const float* __restrict__ w1, const float* __restrict__ w2) {
    int idx = blockIdx.x * 256 + threadIdx.x;
    if (idx >= 2 * 9 * 64 * 64) return;
    int conv = idx / 36864;
    int r    = idx % 36864;
    int tap  = r / 4096;
    int r2   = r % 4096;
    int co = r2 >> 6, ci = r2 & 63;
    const float* w = conv ? w2 : w1;
    float v = w[(co * 64 + ci) * 9 + tap];
    g_w[(size_t)(conv * 9 + tap) * 4096 + ci * 64 + co] =
        __half_as_ushort(__float2half_rn(v));
}

// ------------------------- conv via warp MMA (fp16, single pass) -------------
// Warp tile: 32 px x 64 co. CTA: 128 px, 4 warps.
// MODE 1: g_xh -> g_oh = fp16( md ? gelu(conv+b1) : x )  [fused md + ring mirror]
// MODE 2: g_oh -> d_out = sd ? gelu(conv+b2)+x : gelu(dw(x)+b3)+x  [coalesced dw]
template <int MODE>
__global__ void __launch_bounds__(NTHR, 3) conv_mma(
    const float* __restrict__ xres,
    const float* __restrict__ bias,
    const float* __restrict__ mask,
    const float* __restrict__ w3,
    const float* __restrict__ b3,
    float* __restrict__ out)
{
    extern __shared__ __align__(16) char smem[];
    const uint32_t sb = smem_u32(smem);
    const int tid = threadIdx.x;
    const int warp = tid >> 5, lane = tid & 31;
    const int x0 = blockIdx.x * MPX;
    const int y  = blockIdx.y;

    const __half* xin = (MODE == 1) ? g_xh : g_oh;
    const ushort_t* wbase = g_w + (size_t)((MODE == 1) ? 0 : 9) * 4096;

    // MODE 2: stage depthwise weights/bias once
    if (MODE == 2) {
        float* w3s = reinterpret_cast<float*>(smem + SM_W3);
        float* b3s = reinterpret_cast<float*>(smem + SM_B3);
        if (tid < 64) {
            #pragma unroll
            for (int t = 0; t < 9; t++) w3s[t * 64 + tid] = w3[tid * 9 + t];
            b3s[tid] = b3[tid];
        }
    }

    const uint32_t a_off = (uint32_t)(lane & 15) * ASTRIDE + (uint32_t)(lane >> 4) * 16;
    const uint32_t b_off = (uint32_t)((lane & 7) + ((lane >> 3) & 1) * 8) * ASTRIDE
                         + (uint32_t)(lane >> 4) * 16;

    float acc[2][8][4];
    #pragma unroll
    for (int mt = 0; mt < 2; mt++)
        #pragma unroll
        for (int nt = 0; nt < 8; nt++)
            #pragma unroll
            for (int i = 0; i < 4; i++) acc[mt][nt][i] = 0.0f;

    for (int dyi = 0; dyi < 3; dyi++) {
        __syncthreads();
        // ---- stage A: padded row y + 2*dyi, APX px ----
        {
            const char* src = reinterpret_cast<const char*>(
                &xin[((size_t)(y + 2 * dyi) * PW + x0) * 64]);
            #pragma unroll
            for (int it = 0; it < 9; it++) {
                int i = tid + it * NTHR;
                if (i < APX * 8) {
                    int px = i >> 3, seg = i & 7;
                    cp16(sb + SM_A + px * ASTRIDE + seg * 16, src + i * 16);
                }
            }
        }
        // ---- stage B: 3 taps of this dy-row ----
        {
            const char* src = reinterpret_cast<const char*>(wbase + (size_t)(3 * dyi) * 4096);
            #pragma unroll
            for (int it = 0; it < 12; it++) {
                int i = tid + it * NTHR;
                int slot = i >> 9;
                int rem  = i & 511;
                int ci = rem >> 3, seg = rem & 7;
                cp16(sb + SM_B + slot * BSLOT + ci * ASTRIDE + seg * 16, src + i * 16);
            }
        }
        cp_commit_wait();
        __syncthreads();

        #pragma unroll
        for (int dxi = 0; dxi < 3; dxi++) {
            const uint32_t am0 = sb + SM_A + (uint32_t)(32 * warp + 2 * dxi) * ASTRIDE + a_off;
            const uint32_t bb  = sb + SM_B + (uint32_t)dxi * BSLOT + b_off;
            #pragma unroll
            for (int kc = 0; kc < 64; kc += 16) {
                uint32_t ah0[4], ah1[4];
                ldsm4(ah0, am0 + kc * 2);
                ldsm4(ah1, am0 + 16 * ASTRIDE + kc * 2);
                const uint32_t bbase = bb + (uint32_t)kc * ASTRIDE;
                #pragma unroll
                for (int nb = 0; nb < 4; nb++) {
                    uint32_t bh[4];
                    ldsm4t(bh, bbase + nb * 32);
                    mma16816(acc[0][2*nb],   ah0, bh[0], bh[1]);
                    mma16816(acc[0][2*nb+1], ah0, bh[2], bh[3]);
                    mma16816(acc[1][2*nb],   ah1, bh[0], bh[1]);
                    mma16816(acc[1][2*nb+1], ah1, bh[2], bh[3]);
                }
            }
        }
    }

    // ---- epilogue: fragments -> smem (pixel-major) ----
    __syncthreads();
    float* sepi = reinterpret_cast<float*>(smem);
    #pragma unroll
    for (int mt = 0; mt < 2; mt++) {
        const int r = 32 * warp + 16 * mt + (lane >> 2);
        #pragma unroll
        for (int nt = 0; nt < 8; nt++) {
            const int c = 8 * nt + 2 * (lane & 3);
            sepi[r * EPI_STRIDE + c]           = acc[mt][nt][0];
            sepi[r * EPI_STRIDE + c + 1]       = acc[mt][nt][1];
            sepi[(r + 8) * EPI_STRIDE + c]     = acc[mt][nt][2];
            sepi[(r + 8) * EPI_STRIDE + c + 1] = acc[mt][nt][3];
        }
    }

    const int m = tid;                 // this thread's pixel
    const int x = x0 + m;
    const int p = y * WW + x;

    if (MODE == 1) {
        // fused mask dilation: stage clipped 5x132 mask window
        float* smask = reinterpret_cast<float*>(smem + SM_MASK);
        for (int i = tid; i < 5 * 132; i += NTHR) {
            int r = i / 132, c = i - r * 132;
            int gy = y - 2 + r, gx = x0 - 2 + c;
            smask[i] = ((unsigned)gy < HH && (unsigned)gx < WW)
                     ? mask[gy * WW + gx] : 0.0f;
        }
        __syncthreads();
        const float* arow = &sepi[m * EPI_STRIDE];
        float mx = 0.0f;
        #pragma unroll
        for (int r = 0; r < 5; r++)
            #pragma unroll
            for (int c = 0; c < 5; c++)
                mx = fmaxf(mx, smask[r * 132 + m + c]);
        const bool md = mx > 0.5f;

        const size_t ob = ((size_t)(y + 2) * PW + (x + 2)) * 64;
        uint4 v[8];
        if (md) {
            #pragma unroll
            for (int i = 0; i < 8; i++) {
                uint32_t w[4];
                #pragma unroll
                for (int q = 0; q < 4; q++) {
                    const int c0 = 8 * i + 2 * q;
                    float v0 = gelu_exact(arow[c0]     + __ldg(&bias[c0]));
                    float v1 = gelu_exact(arow[c0 + 1] + __ldg(&bias[c0 + 1]));
                    w[q] = (uint32_t)__half_as_ushort(__float2half_rn(v0))
                         | ((uint32_t)__half_as_ushort(__float2half_rn(v1)) << 16);
                }
                v[i] = make_uint4(w[0], w[1], w[2], w[3]);
            }
        } else {
            const uint4* shp = reinterpret_cast<const uint4*>(&g_xh[ob]);
            #pragma unroll
            for (int i = 0; i < 8; i++) v[i] = shp[i];
        }
        uint4* dh = reinterpret_cast<uint4*>(&g_oh[ob]);
        #pragma unroll
        for (int i = 0; i < 8; i++) dh[i] = v[i];

        // fused reflect-ring mirror
        int yr = -1, xr = -1;
        if (y == 1 || y == 2) yr = 2 - y;
        else if (y == 509 || y == 510) yr = 1024 - y;
        if (x == 1 || x == 2) xr = 2 - x;
        else if (x == 509 || x == 510) xr = 1024 - x;
        if (yr >= 0) {
            uint4* d = reinterpret_cast<uint4*>(&g_oh[((size_t)yr * PW + (x + 2)) * 64]);
            #pragma unroll
            for (int i = 0; i < 8; i++) d[i] = v[i];
        }
        if (xr >= 0) {
            uint4* d = reinterpret_cast<uint4*>(&g_oh[((size_t)(y + 2) * PW + xr) * 64]);
            #pragma unroll
            for (int i = 0; i < 8; i++) d[i] = v[i];
        }
        if (yr >= 0 && xr >= 0) {
            uint4* d = reinterpret_cast<uint4*>(&g_oh[((size_t)yr * PW + xr) * 64]);
            #pragma unroll
            for (int i = 0; i < 8; i++) d[i] = v[i];
        }
    } else {
        // ---- MODE 2: flags, coalesced dw into sepi at ~sd pixels, unified write
        unsigned char* sflag = reinterpret_cast<unsigned char*>(smem + SM_FLAG);
        const bool sd = mask[p] > 0.5f;
        sflag[m] = sd ? 1 : 0;
        __syncthreads();

        const float* w3s = reinterpret_cast<const float*>(smem + SM_W3);
        const float* b3s = reinterpret_cast<const float*>(smem + SM_B3);

        // cooperative dw: 8 threads per pixel (thread = (px, seg)); 16 px per pass
        const int seg = tid & 7;
        #pragma unroll
        for (int pass = 0; pass < 8; pass++) {
            const int px = pass * 16 + (tid >> 3);
            if (!sflag[px]) {
                const int gx2 = x0 + px;
                float a8[8];
                #pragma unroll
                for (int i = 0; i < 8; i++) a8[i] = 0.0f;
                #pragma unroll
                for (int t = 0; t < 9; t++) {
                    const size_t pos =
                        ((size_t)(y + 2 * (t / 3)) * PW + (gx2 + 2 * (t % 3))) * 64 + seg * 8;
                    uint4 v = *reinterpret_cast<const uint4*>(&g_xh[pos]);
                    const __half2* h = reinterpret_cast<const __half2*>(&v);
                    const float* wr = &w3s[t * 64 + seg * 8];
                    #pragma unroll
                    for (int j = 0; j < 4; j++) {
                        float2 f = __half22float2(h[j]);
                        a8[2*j]     = fmaf(f.x, wr[2*j],     a8[2*j]);
                        a8[2*j + 1] = fmaf(f.y, wr[2*j + 1], a8[2*j + 1]);
                    }
                }
                float* d = &sepi[px * EPI_STRIDE + seg * 8];
                #pragma unroll
                for (int j = 0; j < 8; j++) d[j] = a8[j];
            }
        }
        __syncthreads();

        // unified coalesced write in two 32-channel chunks with batched
        // xres prefetch (MLP=32) to hide LDG latency
        const float* arow = &sepi[m * EPI_STRIDE];
        #pragma unroll
        for (int half = 0; half < 2; half++) {
            float xr[32];
            #pragma unroll
            for (int j = 0; j < 32; j++)
                xr[j] = xres[(size_t)(half * 32 + j) * HW + p];
            #pragma unroll
            for (int j = 0; j < 32; j++) {
                const int c = half * 32 + j;
                const float b = sd ? __ldg(&bias[c]) : b3s[c];
                out[(size_t)c * HW + p] = gelu_exact(arow[c] + b) + xr[j];
            }
        }
    }
}

// ------------------------- launch --------------------------------------------
extern "C" void kernel_launch(void* const* d_in, const int* in_sizes, int n_in,
                              void* d_out, int out_size) {
    const float* x    = (const float*)d_in[0];
    const float* mask = (const float*)d_in[1];
    const float* w1   = (const float*)d_in[2];
    const float* b1   = (const float*)d_in[3];
    const float* w2   = (const float*)d_in[4];
    const float* b2   = (const float*)d_in[5];
    const float* w3   = (const float*)d_in[6];
    const float* b3   = (const float*)d_in[7];
    float* out = (float*)d_out;

    static bool attr_set = false;
    if (!attr_set) {
        cudaFuncSetAttribute(conv_mma<1>,
            cudaFuncAttributeMaxDynamicSharedMemorySize, SM_TOTAL);
        cudaFuncSetAttribute(conv_mma<2>,
            cudaFuncAttributeMaxDynamicSharedMemorySize, SM_TOTAL);
        attr_set = true;
    }

    prep_w<<<(2 * 9 * 64 * 64 + 255) / 256, 256>>>(w1, w2);
    prep_x<<<dim3((PW + 31) / 32, PW), 256>>>(x);

    dim3 cgrid(WW / MPX, HH);   // 4 x 512

    conv_mma<1><<<cgrid, NTHR, SM_TOTAL>>>(x, b1, mask, w3, b3, out);
    conv_mma<2><<<cgrid, NTHR, SM_TOTAL>>>(x, b2, mask, w3, b3, out);
}

// round 17
// speedup vs baseline: 1.1359x; 1.0212x over previous
#include <cuda_runtime.h>
#include <cuda_fp16.h>
#include <math.h>
#include <stdint.h>

#define HH 512
#define WW 512
#define CC 64
#define HW (HH*WW)
#define PW 516                 // padded H/W (reflect pad 2 materialized)
#define MPX 128                // pixels per CTA tile
#define NTHR 128

// smem layout (bytes)
#define ASTRIDE 144            // 64 ch * 2B payload, padded (ldmatrix conflict-free)
#define APX 132                // staged pixels per row (128 + halo 4)
#define SM_A    0
#define SM_B    (APX * ASTRIDE)                 // 19008
#define BSLOT   (64 * ASTRIDE)                  // 9216 per tap
#define SM_W3   (SM_B + 3 * BSLOT)              // 46656
#define SM_B3   (SM_W3 + 2304)                  // 48960
#define SM_TOTAL (SM_B3 + 256)                  // 49216
#define EPI_STRIDE 65                           // MODE1 epi stride (floats)
#define SM_FLAG 33280                           // 128 bytes (MODE2 sd flags)
#define SM_MASK 33408                           // 5*132 floats (MODE1) -> ends 36048

typedef unsigned short ushort_t;

// ------------------------- device globals (no allocation) -------------------
__device__ __half g_xh[(size_t)PW * PW * CC];   // x, padded NHWC fp16
__device__ __half g_oh[(size_t)PW * PW * CC];   // x_ori, padded NHWC fp16
__device__ ushort_t g_w[2 * 9 * 4096];          // [conv][tap][ci*64+co] fp16

// ------------------------- helpers ------------------------------------------
__device__ __forceinline__ int reflect512(int i) {
    i = abs(i);
    return min(i, 1022 - i);
}
__device__ __forceinline__ float gelu_exact(float v) {
    return 0.5f * v * (1.0f + erff(v * 0.70710678118654752f));
}
__device__ __forceinline__ uint32_t smem_u32(const void* p) {
    uint32_t a;
    asm("{ .reg .u64 t; cvta.to.shared.u64 t, %1; cvt.u32.u64 %0, t; }" : "=r"(a) : "l"(p));
    return a;
}
__device__ __forceinline__ void cp16(uint32_t dst, const void* src) {
    asm volatile("cp.async.cg.shared.global [%0], [%1], 16;" :: "r"(dst), "l"(src));
}
__device__ __forceinline__ void cp_commit_wait() {
    asm volatile("cp.async.commit_group;");
    asm volatile("cp.async.wait_group 0;");
}
__device__ __forceinline__ void ldsm4(uint32_t (&r)[4], uint32_t addr) {
    asm volatile("ldmatrix.sync.aligned.m8n8.x4.shared.b16 {%0,%1,%2,%3}, [%4];"
                 : "=r"(r[0]), "=r"(r[1]), "=r"(r[2]), "=r"(r[3]) : "r"(addr));
}
__device__ __forceinline__ void ldsm4t(uint32_t (&r)[4], uint32_t addr) {
    asm volatile("ldmatrix.sync.aligned.m8n8.x4.trans.shared.b16 {%0,%1,%2,%3}, [%4];"
                 : "=r"(r[0]), "=r"(r[1]), "=r"(r[2]), "=r"(r[3]) : "r"(addr));
}
__device__ __forceinline__ void mma16816(float (&d)[4], const uint32_t (&a)[4],
                                         uint32_t b0, uint32_t b1) {
    asm volatile(
        "mma.sync.aligned.m16n8k16.row.col.f32.f16.f16.f32 "
        "{%0,%1,%2,%3}, {%4,%5,%6,%7}, {%8,%9}, {%0,%1,%2,%3};"
        : "+f"(d[0]), "+f"(d[1]), "+f"(d[2]), "+f"(d[3])
        : "r"(a[0]), "r"(a[1]), "r"(a[2]), "r"(a[3]), "r"(b0), "r"(b1));
}

// ------------------------- prepasses -----------------------------------------
// x (NCHW fp32) -> padded NHWC fp16
__global__ void prep_x(const float* __restrict__ x) {
    __shared__ ushort_t sh[32][66];
    const int yp  = blockIdx.y;
    const int xp0 = blockIdx.x * 32;
    const int tid = threadIdx.x;
    const int warp = tid >> 5, lane = tid & 31;
    const int ry = reflect512(yp - 2);
    const int xp = xp0 + lane;
    const int rx = reflect512((xp < PW ? xp : PW - 1) - 2);
    #pragma unroll
    for (int q = 0; q < 8; q++) {
        int ci = warp * 8 + q;
        float v = x[(size_t)ci * HW + (size_t)ry * WW + rx];
        sh[lane][ci] = __half_as_ushort(__float2half_rn(v));
    }
    __syncthreads();
    const int jj = tid >> 3, c0 = (tid & 7) * 8;
    const int xpw = xp0 + jj;
    if (xpw < PW) {
        size_t base = ((size_t)yp * PW + xpw) * 64 + c0;
        uint32_t a[4];
        #pragma unroll
        for (int i = 0; i < 4; i++)
            a[i] = (uint32_t)sh[jj][c0 + 2*i] | ((uint32_t)sh[jj][c0 + 2*i + 1] << 16);
        *reinterpret_cast<uint4*>(&g_xh[base]) = make_uint4(a[0], a[1], a[2], a[3]);
    }
}

// weights -> [conv][tap][ci][co] fp16
__global__ void prep_w(const float* __restrict__ w1, const float* __restrict__ w2) {
    int idx = blockIdx.x * 256 + threadIdx.x;
    if (idx >= 2 * 9 * 64 * 64) return;
    int conv = idx / 36864;
    int r    = idx % 36864;
    int tap  = r / 4096;
    int r2   = r % 4096;
    int co = r2 >> 6, ci = r2 & 63;
    const float* w = conv ? w2 : w1;
    float v = w[(co * 64 + ci) * 9 + tap];
    g_w[(size_t)(conv * 9 + tap) * 4096 + ci * 64 + co] =
        __half_as_ushort(__float2half_rn(v));
}

// ------------------------- conv via warp MMA (fp16, single pass) -------------
// Warp tile: 32 px x 64 co. CTA: 128 px, 4 warps.
// MODE 1: g_xh -> g_oh = fp16( md ? gelu(conv+b1) : x )  [fused md + ring mirror]
// MODE 2: g_oh -> d_out = sd ? gelu(conv+b2)+x : gelu(dw(x)+b3)+x
//         (swizzled sepi, vectorized 4px x 16ch final write)
template <int MODE>
__global__ void __launch_bounds__(NTHR, 3) conv_mma(
    const float* __restrict__ xres,
    const float* __restrict__ bias,
    const float* __restrict__ mask,
    const float* __restrict__ w3,
    const float* __restrict__ b3,
    float* __restrict__ out)
{
    extern __shared__ __align__(16) char smem[];
    const uint32_t sb = smem_u32(smem);
    const int tid = threadIdx.x;
    const int warp = tid >> 5, lane = tid & 31;
    const int x0 = blockIdx.x * MPX;
    const int y  = blockIdx.y;

    const __half* xin = (MODE == 1) ? g_xh : g_oh;
    const ushort_t* wbase = g_w + (size_t)((MODE == 1) ? 0 : 9) * 4096;

    // MODE 2: stage depthwise weights/bias once
    if (MODE == 2) {
        float* w3s = reinterpret_cast<float*>(smem + SM_W3);
        float* b3s = reinterpret_cast<float*>(smem + SM_B3);
        if (tid < 64) {
            #pragma unroll
            for (int t = 0; t < 9; t++) w3s[t * 64 + tid] = w3[tid * 9 + t];
            b3s[tid] = b3[tid];
        }
    }

    const uint32_t a_off = (uint32_t)(lane & 15) * ASTRIDE + (uint32_t)(lane >> 4) * 16;
    const uint32_t b_off = (uint32_t)((lane & 7) + ((lane >> 3) & 1) * 8) * ASTRIDE
                         + (uint32_t)(lane >> 4) * 16;

    float acc[2][8][4];
    #pragma unroll
    for (int mt = 0; mt < 2; mt++)
        #pragma unroll
        for (int nt = 0; nt < 8; nt++)
            #pragma unroll
            for (int i = 0; i < 4; i++) acc[mt][nt][i] = 0.0f;

    for (int dyi = 0; dyi < 3; dyi++) {
        __syncthreads();
        // ---- stage A: padded row y + 2*dyi, APX px ----
        {
            const char* src = reinterpret_cast<const char*>(
                &xin[((size_t)(y + 2 * dyi) * PW + x0) * 64]);
            #pragma unroll
            for (int it = 0; it < 9; it++) {
                int i = tid + it * NTHR;
                if (i < APX * 8) {
                    int px = i >> 3, seg = i & 7;
                    cp16(sb + SM_A + px * ASTRIDE + seg * 16, src + i * 16);
                }
            }
        }
        // ---- stage B: 3 taps of this dy-row ----
        {
            const char* src = reinterpret_cast<const char*>(wbase + (size_t)(3 * dyi) * 4096);
            #pragma unroll
            for (int it = 0; it < 12; it++) {
                int i = tid + it * NTHR;
                int slot = i >> 9;
                int rem  = i & 511;
                int ci = rem >> 3, seg = rem & 7;
                cp16(sb + SM_B + slot * BSLOT + ci * ASTRIDE + seg * 16, src + i * 16);
            }
        }
        cp_commit_wait();
        __syncthreads();

        #pragma unroll
        for (int dxi = 0; dxi < 3; dxi++) {
            const uint32_t am0 = sb + SM_A + (uint32_t)(32 * warp + 2 * dxi) * ASTRIDE + a_off;
            const uint32_t bb  = sb + SM_B + (uint32_t)dxi * BSLOT + b_off;
            #pragma unroll
            for (int kc = 0; kc < 64; kc += 16) {
                uint32_t ah0[4], ah1[4];
                ldsm4(ah0, am0 + kc * 2);
                ldsm4(ah1, am0 + 16 * ASTRIDE + kc * 2);
                const uint32_t bbase = bb + (uint32_t)kc * ASTRIDE;
                #pragma unroll
                for (int nb = 0; nb < 4; nb++) {
                    uint32_t bh[4];
                    ldsm4t(bh, bbase + nb * 32);
                    mma16816(acc[0][2*nb],   ah0, bh[0], bh[1]);
                    mma16816(acc[0][2*nb+1], ah0, bh[2], bh[3]);
                    mma16816(acc[1][2*nb],   ah1, bh[0], bh[1]);
                    mma16816(acc[1][2*nb+1], ah1, bh[2], bh[3]);
                }
            }
        }
    }

    // epi index: MODE1 = stride 65 (scalar-friendly); MODE2 = stride 64 + XOR
    // swizzle on bits 2-4 of channel, keyed by px>>2 (float4-friendly).
    auto eidx = [](int r, int c) -> int {
        return (MODE == 1) ? r * EPI_STRIDE + c
                           : r * 64 + (c ^ (((r >> 2) & 7) << 2));
    };

    // ---- epilogue: fragments -> smem (pixel-major) ----
    __syncthreads();
    float* sepi = reinterpret_cast<float*>(smem);
    #pragma unroll
    for (int mt = 0; mt < 2; mt++) {
        const int r = 32 * warp + 16 * mt + (lane >> 2);
        #pragma unroll
        for (int nt = 0; nt < 8; nt++) {
            const int c = 8 * nt + 2 * (lane & 3);
            const int i0 = eidx(r, c);
            const int i1 = eidx(r + 8, c);
            sepi[i0]     = acc[mt][nt][0];
            sepi[i0 + 1] = acc[mt][nt][1];
            sepi[i1]     = acc[mt][nt][2];
            sepi[i1 + 1] = acc[mt][nt][3];
        }
    }

    const int m = tid;                 // this thread's pixel
    const int x = x0 + m;
    const int p = y * WW + x;

    if (MODE == 1) {
        // fused mask dilation: stage clipped 5x132 mask window
        float* smask = reinterpret_cast<float*>(smem + SM_MASK);
        for (int i = tid; i < 5 * 132; i += NTHR) {
            int r = i / 132, c = i - r * 132;
            int gy = y - 2 + r, gx = x0 - 2 + c;
            smask[i] = ((unsigned)gy < HH && (unsigned)gx < WW)
                     ? mask[gy * WW + gx] : 0.0f;
        }
        __syncthreads();
        const float* arow = &sepi[m * EPI_STRIDE];
        float mx = 0.0f;
        #pragma unroll
        for (int r = 0; r < 5; r++)
            #pragma unroll
            for (int c = 0; c < 5; c++)
                mx = fmaxf(mx, smask[r * 132 + m + c]);
        const bool md = mx > 0.5f;

        const size_t ob = ((size_t)(y + 2) * PW + (x + 2)) * 64;
        uint4 v[8];
        if (md) {
            #pragma unroll
            for (int i = 0; i < 8; i++) {
                uint32_t w[4];
                #pragma unroll
                for (int q = 0; q < 4; q++) {
                    const int c0 = 8 * i + 2 * q;
                    float v0 = gelu_exact(arow[c0]     + __ldg(&bias[c0]));
                    float v1 = gelu_exact(arow[c0 + 1] + __ldg(&bias[c0 + 1]));
                    w[q] = (uint32_t)__half_as_ushort(__float2half_rn(v0))
                         | ((uint32_t)__half_as_ushort(__float2half_rn(v1)) << 16);
                }
                v[i] = make_uint4(w[0], w[1], w[2], w[3]);
            }
        } else {
            const uint4* shp = reinterpret_cast<const uint4*>(&g_xh[ob]);
            #pragma unroll
            for (int i = 0; i < 8; i++) v[i] = shp[i];
        }
        uint4* dh = reinterpret_cast<uint4*>(&g_oh[ob]);
        #pragma unroll
        for (int i = 0; i < 8; i++) dh[i] = v[i];

        // fused reflect-ring mirror
        int yr = -1, xr = -1;
        if (y == 1 || y == 2) yr = 2 - y;
        else if (y == 509 || y == 510) yr = 1024 - y;
        if (x == 1 || x == 2) xr = 2 - x;
        else if (x == 509 || x == 510) xr = 1024 - x;
        if (yr >= 0) {
            uint4* d = reinterpret_cast<uint4*>(&g_oh[((size_t)yr * PW + (x + 2)) * 64]);
            #pragma unroll
            for (int i = 0; i < 8; i++) d[i] = v[i];
        }
        if (xr >= 0) {
            uint4* d = reinterpret_cast<uint4*>(&g_oh[((size_t)(y + 2) * PW + xr) * 64]);
            #pragma unroll
            for (int i = 0; i < 8; i++) d[i] = v[i];
        }
        if (yr >= 0 && xr >= 0) {
            uint4* d = reinterpret_cast<uint4*>(&g_oh[((size_t)yr * PW + xr) * 64]);
            #pragma unroll
            for (int i = 0; i < 8; i++) d[i] = v[i];
        }
    } else {
        // ---- MODE 2: flags, coalesced dw into sepi at ~sd pixels, vector write
        unsigned char* sflag = reinterpret_cast<unsigned char*>(smem + SM_FLAG);
        const bool sd = mask[p] > 0.5f;
        sflag[m] = sd ? 1 : 0;
        __syncthreads();

        const float* w3s = reinterpret_cast<const float*>(smem + SM_W3);
        const float* b3s = reinterpret_cast<const float*>(smem + SM_B3);

        // cooperative dw: 8 threads per pixel (thread = (px, seg)); 16 px per pass
        const int seg = tid & 7;
        #pragma unroll
        for (int pass = 0; pass < 8; pass++) {
            const int px = pass * 16 + (tid >> 3);
            if (!sflag[px]) {
                const int gx2 = x0 + px;
                float a8[8];
                #pragma unroll
                for (int i = 0; i < 8; i++) a8[i] = 0.0f;
                #pragma unroll
                for (int t = 0; t < 9; t++) {
                    const size_t pos =
                        ((size_t)(y + 2 * (t / 3)) * PW + (gx2 + 2 * (t % 3))) * 64 + seg * 8;
                    uint4 v = *reinterpret_cast<const uint4*>(&g_xh[pos]);
                    const __half2* h = reinterpret_cast<const __half2*>(&v);
                    const float* wr = &w3s[t * 64 + seg * 8];
                    #pragma unroll
                    for (int j = 0; j < 4; j++) {
                        float2 f = __half22float2(h[j]);
                        a8[2*j]     = fmaf(f.x, wr[2*j],     a8[2*j]);
                        a8[2*j + 1] = fmaf(f.y, wr[2*j + 1], a8[2*j + 1]);
                    }
                }
                // swizzled float4 stores (bits 2-4 flip; 4-float blocks intact)
                const int sw = ((px >> 2) & 7) << 2;
                *reinterpret_cast<float4*>(&sepi[px * 64 + ((seg * 8) ^ sw)]) =
                    make_float4(a8[0], a8[1], a8[2], a8[3]);
                *reinterpret_cast<float4*>(&sepi[px * 64 + ((seg * 8 + 4) ^ sw)]) =
                    make_float4(a8[4], a8[5], a8[6], a8[7]);
            }
        }
        __syncthreads();

        // vectorized unified write: thread = 4 consecutive px x 16 ch
        const int lq = tid & 31;
        const int pg = lq * 4;             // pixel group base
        const int cb = (tid >> 5) * 16;    // channel base
        const int p0 = y * WW + x0 + pg;
        const int swzv = (lq & 7) << 2;    // (pg+j)>>2 == lq for j<4
        bool sd4[4];
        #pragma unroll
        for (int j = 0; j < 4; j++) sd4[j] = (sflag[pg + j] != 0);

        #pragma unroll
        for (int cq = 0; cq < 4; cq++) {
            const int c = cb + 4 * cq;
            float s[4][4];
            #pragma unroll
            for (int j = 0; j < 4; j++) {
                float4 t = *reinterpret_cast<const float4*>(
                    &sepi[(pg + j) * 64 + (c ^ swzv)]);
                s[j][0] = t.x; s[j][1] = t.y; s[j][2] = t.z; s[j][3] = t.w;
            }
            float4 xr4[4];
            #pragma unroll
            for (int k = 0; k < 4; k++)
                xr4[k] = *reinterpret_cast<const float4*>(&xres[(size_t)(c + k) * HW + p0]);
            #pragma unroll
            for (int k = 0; k < 4; k++) {
                const int ck = c + k;
                const float b2 = __ldg(&bias[ck]);
                const float bv = b3s[ck];
                float4 o;
                o.x = gelu_exact(s[0][k] + (sd4[0] ? b2 : bv)) + xr4[k].x;
                o.y = gelu_exact(s[1][k] + (sd4[1] ? b2 : bv)) + xr4[k].y;
                o.z = gelu_exact(s[2][k] + (sd4[2] ? b2 : bv)) + xr4[k].z;
                o.w = gelu_exact(s[3][k] + (sd4[3] ? b2 : bv)) + xr4[k].w;
                *reinterpret_cast<float4*>(&out[(size_t)ck * HW + p0]) = o;
            }
        }
    }
}

// ------------------------- launch --------------------------------------------
extern "C" void kernel_launch(void* const* d_in, const int* in_sizes, int n_in,
                              void* d_out, int out_size) {
    const float* x    = (const float*)d_in[0];
    const float* mask = (const float*)d_in[1];
    const float* w1   = (const float*)d_in[2];
    const float* b1   = (const float*)d_in[3];
    const float* w2   = (const float*)d_in[4];
    const float* b2   = (const float*)d_in[5];
    const float* w3   = (const float*)d_in[6];
    const float* b3   = (const float*)d_in[7];
    float* out = (float*)d_out;

    static bool attr_set = false;
    if (!attr_set) {
        cudaFuncSetAttribute(conv_mma<1>,
            cudaFuncAttributeMaxDynamicSharedMemorySize, SM_TOTAL);
        cudaFuncSetAttribute(conv_mma<2>,
            cudaFuncAttributeMaxDynamicSharedMemorySize, SM_TOTAL);
        attr_set = true;
    }

    prep_w<<<(2 * 9 * 64 * 64 + 255) / 256, 256>>>(w1, w2);
    prep_x<<<dim3((PW + 31) / 32, PW), 256>>>(x);

    dim3 cgrid(WW / MPX, HH);   // 4 x 512

    conv_mma<1><<<cgrid, NTHR, SM_TOTAL>>>(x, b1, mask, w3, b3, out);
    conv_mma<2><<<cgrid, NTHR, SM_TOTAL>>>(x, b2, mask, w3, b3, out);
}